// round 1
// baseline (speedup 1.0000x reference)
#include <cuda_runtime.h>
#include <math.h>

#define NB 64
#define V 256
#define F 64
#define C 64
#define ALPHA_C 0.1f

// ---------------- scratch (no allocations allowed) ----------------
__device__ float g_colsum[NB * V];
__device__ float g_A[NB * V];
__device__ float g_B[NB * V];
__device__ float g_r[NB * V];
__device__ float g_lossP[NB];
__device__ float g_P[NB * V * F];   // s @ x
__device__ float g_Q[NB * V * F];   // (s*s) @ x

// ---------------- stage 0: zero accumulators ----------------
__global__ void zero_kernel() {
    int i = blockIdx.x * blockDim.x + threadIdx.x;
    if (i < NB * V) {
        g_colsum[i] = 0.f;
        g_A[i] = 0.f;
        g_B[i] = 0.f;
    }
    if (i < NB) g_lossP[i] = 0.f;
}

// ---------------- stage 1: pairwise score/d2, tmp_s, column stats ----------------
// Grid: (jt=4, it=4, b=64); 256 threads; 64x64 (i,j) tile per block.
__global__ __launch_bounds__(256) void pairwise_kernel(
    const float* __restrict__ x, const float* __restrict__ a,
    float* __restrict__ s_out /* tmp_s written here, normalized later */) {
    __shared__ float xi_t[F][68];  // [f][i] transposed, pad 68 keeps 16B alignment
    __shared__ float xj_t[F][68];
    __shared__ float a_s[F];
    __shared__ float smc[64], smA[64], smB[64];

    const int b = blockIdx.z, it = blockIdx.y, jt = blockIdx.x;
    const int i0 = it * 64, j0 = jt * 64;
    const int t = threadIdx.x;
    const float* xb = x + b * V * F;

    for (int e = t; e < 64 * F; e += 256) {
        int row = e >> 6;
        int f = e & 63;
        xi_t[f][row] = xb[(i0 + row) * F + f];
        xj_t[f][row] = xb[(j0 + row) * F + f];
    }
    if (t < F) a_s[t] = a[t];
    if (t < 64) { smc[t] = 0.f; smA[t] = 0.f; smB[t] = 0.f; }
    __syncthreads();

    const int tx = t & 15, ty = t >> 4;

    float sc[4][4], dd[4][4];
#pragma unroll
    for (int ii = 0; ii < 4; ii++)
#pragma unroll
        for (int jj = 0; jj < 4; jj++) { sc[ii][jj] = 0.f; dd[ii][jj] = 0.f; }

#pragma unroll 4
    for (int f = 0; f < F; f++) {
        float4 xi4 = *(const float4*)&xi_t[f][ty * 4];
        float4 xj4 = *(const float4*)&xj_t[f][tx * 4];
        float xiv[4] = {xi4.x, xi4.y, xi4.z, xi4.w};
        float xjv[4] = {xj4.x, xj4.y, xj4.z, xj4.w};
        float af = a_s[f];
#pragma unroll
        for (int ii = 0; ii < 4; ii++)
#pragma unroll
            for (int jj = 0; jj < 4; jj++) {
                float d = xiv[ii] - xjv[jj];
                sc[ii][jj] = fmaf(fabsf(d), af, sc[ii][jj]);
                dd[ii][jj] = fmaf(d, d, dd[ii][jj]);
            }
    }

    float cpart[4] = {0.f, 0.f, 0.f, 0.f};
    float Apart[4] = {0.f, 0.f, 0.f, 0.f};
    float Bpart[4] = {0.f, 0.f, 0.f, 0.f};

    float* srow_base = s_out + (size_t)b * V * V;
#pragma unroll
    for (int ii = 0; ii < 4; ii++) {
        float tv[4];
#pragma unroll
        for (int jj = 0; jj < 4; jj++) {
            float tmp = expf(-fmaxf(sc[ii][jj], 0.f));
            tv[jj] = tmp;
            cpart[jj] += tmp;
            Apart[jj] += tmp * tmp;
            Bpart[jj] += tmp * dd[ii][jj];
        }
        float4 o = make_float4(tv[0], tv[1], tv[2], tv[3]);
        *(float4*)&srow_base[(i0 + ty * 4 + ii) * V + j0 + tx * 4] = o;
    }

#pragma unroll
    for (int jj = 0; jj < 4; jj++) {
        atomicAdd(&smc[tx * 4 + jj], cpart[jj]);
        atomicAdd(&smA[tx * 4 + jj], Apart[jj]);
        atomicAdd(&smB[tx * 4 + jj], Bpart[jj]);
    }
    __syncthreads();
    if (t < 64) {
        atomicAdd(&g_colsum[b * V + j0 + t], smc[t]);
        atomicAdd(&g_A[b * V + j0 + t], smA[t]);
        atomicAdd(&g_B[b * V + j0 + t], smB[t]);
    }
}

// ---------------- stage 2: per-column recip + per-batch loss partial ----------------
__global__ void colstats_kernel() {
    int b = blockIdx.x;
    int j = threadIdx.x;  // 256 threads
    float cs = g_colsum[b * V + j];
    float r = 1.0f / cs;
    g_r[b * V + j] = r;
    float part = g_A[b * V + j] * r * r + ALPHA_C * g_B[b * V + j] * r;
    __shared__ float red[256];
    red[j] = part;
    __syncthreads();
    for (int s = 128; s > 0; s >>= 1) {
        if (j < s) red[j] += red[j + s];
        __syncthreads();
    }
    if (j == 0) g_lossP[b] = red[0];
}

__global__ void loss_final_kernel(float* __restrict__ out_loss) {
    __shared__ float red[64];
    int t = threadIdx.x;  // 64 threads, 1 block
    red[t] = g_lossP[t];
    __syncthreads();
    for (int s = 32; s > 0; s >>= 1) {
        if (t < s) red[t] += red[t + s];
        __syncthreads();
    }
    if (t == 0) *out_loss = red[0];
}

// ---------------- stage 3: normalize s in place (s = tmp_s * r[col]) ----------------
__global__ void normalize_kernel(float* __restrict__ s_out) {
    int vidx = blockIdx.x * blockDim.x + threadIdx.x;  // float4 index, total NB*V*V/4
    int base = vidx * 4;
    int b = base >> 16;       // / (V*V)
    int j = base & (V - 1);   // j % 256, base is 4-aligned
    float4 v = *(float4*)&s_out[base];
    float4 rv = *(const float4*)&g_r[b * V + j];
    v.x *= rv.x; v.y *= rv.y; v.z *= rv.z; v.w *= rv.w;
    *(float4*)&s_out[base] = v;
}

// ---------------- stage 4: P = s@x, Q = (s*s)@x (shared operand loads) ----------------
// Grid: (it=4, b=64); 256 threads; C-tile 64(i) x 64(f), 4x4 per thread, dual accum.
__global__ __launch_bounds__(256) void pq_gemm_kernel(
    const float* __restrict__ s_out, const float* __restrict__ x) {
    __shared__ float sA[64][68];  // s chunk transposed [k][i]
    __shared__ float sB[64][64];  // x chunk natural [k][f]

    const int b = blockIdx.y, it = blockIdx.x;
    const int i0 = it * 64;
    const int t = threadIdx.x;
    const int tx = t & 15, ty = t >> 4;

    const float* sb = s_out + (size_t)b * V * V;
    const float* xb = x + b * V * F;

    float P[4][4], Q[4][4];
#pragma unroll
    for (int ii = 0; ii < 4; ii++)
#pragma unroll
        for (int jj = 0; jj < 4; jj++) { P[ii][jj] = 0.f; Q[ii][jj] = 0.f; }

    for (int kc = 0; kc < 4; kc++) {
        int k0 = kc * 64;
        for (int q = t; q < 64 * 16; q += 256) {
            int i = q >> 4;
            int k4 = (q & 15) * 4;
            float4 v = *(const float4*)&sb[(i0 + i) * V + k0 + k4];
            sA[k4 + 0][i] = v.x;
            sA[k4 + 1][i] = v.y;
            sA[k4 + 2][i] = v.z;
            sA[k4 + 3][i] = v.w;
        }
        for (int q = t; q < 64 * 16; q += 256) {
            int k = q >> 4;
            int f4 = (q & 15) * 4;
            *(float4*)&sB[k][f4] = *(const float4*)&xb[(k0 + k) * F + f4];
        }
        __syncthreads();
#pragma unroll 4
        for (int k = 0; k < 64; k++) {
            float4 a4 = *(const float4*)&sA[k][ty * 4];
            float4 b4 = *(const float4*)&sB[k][tx * 4];
            float av[4] = {a4.x, a4.y, a4.z, a4.w};
            float bv[4] = {b4.x, b4.y, b4.z, b4.w};
            float a2[4];
#pragma unroll
            for (int u = 0; u < 4; u++) a2[u] = av[u] * av[u];
#pragma unroll
            for (int ii = 0; ii < 4; ii++)
#pragma unroll
                for (int jj = 0; jj < 4; jj++) {
                    P[ii][jj] = fmaf(av[ii], bv[jj], P[ii][jj]);
                    Q[ii][jj] = fmaf(a2[ii], bv[jj], Q[ii][jj]);
                }
        }
        __syncthreads();
    }

    float* pOut = g_P + b * V * F;
    float* qOut = g_Q + b * V * F;
#pragma unroll
    for (int ii = 0; ii < 4; ii++) {
        int row = i0 + ty * 4 + ii;
        *(float4*)&pOut[row * F + tx * 4] = make_float4(P[ii][0], P[ii][1], P[ii][2], P[ii][3]);
        *(float4*)&qOut[row * F + tx * 4] = make_float4(Q[ii][0], Q[ii][1], Q[ii][2], Q[ii][3]);
    }
}

// ---------------- stage 5: out = relu( x@(th0-th2) - P@th1 + Q@(2*th2) ) ----------------
// Grid: (it=4, b=64); 256 threads; 3 sequential passes reusing smem buffers.
__global__ __launch_bounds__(256) void out_gemm_kernel(
    const float* __restrict__ x, const float* __restrict__ theta,
    float* __restrict__ gcn) {
    __shared__ float sTh[64][64];   // [f][c]
    __shared__ float sSrc[64][68];  // [f][i]

    const int b = blockIdx.y, it = blockIdx.x;
    const int i0 = it * 64;
    const int t = threadIdx.x;
    const int tx = t & 15, ty = t >> 4;

    float acc[4][4];
#pragma unroll
    for (int ii = 0; ii < 4; ii++)
#pragma unroll
        for (int jj = 0; jj < 4; jj++) acc[ii][jj] = 0.f;

    for (int m = 0; m < 3; m++) {
        const float* src = (m == 0) ? (x + b * V * F)
                         : (m == 1) ? (g_P + b * V * F)
                                    : (g_Q + b * V * F);
        // theta combos
        for (int q = t; q < 64 * 16; q += 256) {
            int f = q >> 4;
            int c4 = (q & 15) * 4;
            float4 v;
            if (m == 0) {
                float4 t0 = *(const float4*)&theta[(0 * F + f) * C + c4];
                float4 t2 = *(const float4*)&theta[(2 * F + f) * C + c4];
                v = make_float4(t0.x - t2.x, t0.y - t2.y, t0.z - t2.z, t0.w - t2.w);
            } else if (m == 1) {
                float4 t1 = *(const float4*)&theta[(1 * F + f) * C + c4];
                v = make_float4(-t1.x, -t1.y, -t1.z, -t1.w);
            } else {
                float4 t2 = *(const float4*)&theta[(2 * F + f) * C + c4];
                v = make_float4(2.f * t2.x, 2.f * t2.y, 2.f * t2.z, 2.f * t2.w);
            }
            *(float4*)&sTh[f][c4] = v;
        }
        // src transposed
        for (int q = t; q < 64 * 16; q += 256) {
            int i = q >> 4;
            int f4 = (q & 15) * 4;
            float4 v = *(const float4*)&src[(i0 + i) * F + f4];
            sSrc[f4 + 0][i] = v.x;
            sSrc[f4 + 1][i] = v.y;
            sSrc[f4 + 2][i] = v.z;
            sSrc[f4 + 3][i] = v.w;
        }
        __syncthreads();
#pragma unroll 4
        for (int k = 0; k < 64; k++) {
            float4 a4 = *(const float4*)&sSrc[k][ty * 4];
            float4 b4 = *(const float4*)&sTh[k][tx * 4];
            float av[4] = {a4.x, a4.y, a4.z, a4.w};
            float bv[4] = {b4.x, b4.y, b4.z, b4.w};
#pragma unroll
            for (int ii = 0; ii < 4; ii++)
#pragma unroll
                for (int jj = 0; jj < 4; jj++)
                    acc[ii][jj] = fmaf(av[ii], bv[jj], acc[ii][jj]);
        }
        __syncthreads();
    }

#pragma unroll
    for (int ii = 0; ii < 4; ii++) {
        int row = i0 + ty * 4 + ii;
        float4 o = make_float4(fmaxf(acc[ii][0], 0.f), fmaxf(acc[ii][1], 0.f),
                               fmaxf(acc[ii][2], 0.f), fmaxf(acc[ii][3], 0.f));
        *(float4*)&gcn[b * V * C + row * C + tx * 4] = o;
    }
}

// ---------------- launch ----------------
extern "C" void kernel_launch(void* const* d_in, const int* in_sizes, int n_in,
                              void* d_out, int out_size) {
    const float* x = (const float*)d_in[0];      // (64,256,64)
    const float* a = (const float*)d_in[1];      // (64,)
    const float* theta = (const float*)d_in[2];  // (3,64,64)

    float* out = (float*)d_out;
    float* gcn = out;                                 // NB*V*C
    float* s_out = out + (size_t)NB * V * C;          // NB*V*V
    float* loss = out + (size_t)NB * V * C + (size_t)NB * V * V;  // 1

    zero_kernel<<<(NB * V + 255) / 256, 256>>>();

    dim3 g1(4, 4, NB);
    pairwise_kernel<<<g1, 256>>>(x, a, s_out);

    colstats_kernel<<<NB, 256>>>();
    loss_final_kernel<<<1, 64>>>(loss);

    normalize_kernel<<<(NB * V * V / 4) / 256, 256>>>(s_out);

    dim3 g4(4, NB);
    pq_gemm_kernel<<<g4, 256>>>(s_out, x);

    dim3 g5(4, NB);
    out_gemm_kernel<<<g5, 256>>>(x, theta, gcn);
}